// round 2
// baseline (speedup 1.0000x reference)
#include <cuda_runtime.h>
#include <cuda_bf16.h>
#include <cstdint>

// Problem constants
#define NUM_USERS 100000
#define NUM_ITEMS 50000
#define N_NODES   150000
#define EMB_DIM   64
#define TEXT_DIM  384
#define N64 (N_NODES * EMB_DIM)   // 9,600,000 floats per buffer

// Scratch buffers (device globals — allocation is prohibited)
__device__ float g_text0[N64];  // emb_text = text_feats @ W_text + b
__device__ float g_id1[N64];    // spmm layer-1 outputs
__device__ float g_text1[N64];
__device__ float g_id2[N64];    // spmm layer-2 outputs
__device__ float g_text2[N64];

// ---------------------------------------------------------------------------
// Zero the 4 scatter-destination buffers (g_id1/g_text1/g_id2/g_text2)
// ---------------------------------------------------------------------------
__global__ void zero_kernel() {
    int i = blockIdx.x * blockDim.x + threadIdx.x;
    const int n4 = N64 / 4;  // 2.4M float4 per buffer
    if (i < n4) {
        float4 z = make_float4(0.f, 0.f, 0.f, 0.f);
        ((float4*)g_id1)[i]   = z;
        ((float4*)g_text1)[i] = z;
        ((float4*)g_id2)[i]   = z;
        ((float4*)g_text2)[i] = z;
    }
}

// ---------------------------------------------------------------------------
// Text projection GEMM: g_text0[N_NODES,64] = text_feats[N,384] @ W[384,64] + b
// Tiled: BM=128, BN=64, BK=16, 256 threads, 8x4 micro-tile per thread.
// ---------------------------------------------------------------------------
__global__ void gemm_text_kernel(const float* __restrict__ A,
                                 const float* __restrict__ W,
                                 const float* __restrict__ bias) {
    __shared__ float As[16][128];   // k-major
    __shared__ float Bs[16][64];

    const int tid = threadIdx.x;
    const int m0  = blockIdx.x * 128;
    const int tr  = tid >> 4;       // 0..15 -> rows tr*8 .. tr*8+7
    const int tc  = tid & 15;       // 0..15 -> cols tc*4 .. tc*4+3

    float acc[8][4];
    #pragma unroll
    for (int i = 0; i < 8; i++)
        #pragma unroll
        for (int j = 0; j < 4; j++) acc[i][j] = 0.f;

    for (int k0 = 0; k0 < TEXT_DIM; k0 += 16) {
        // Load A tile: 128 rows x 16 k  (512 float4, 2 per thread)
        #pragma unroll
        for (int p = 0; p < 2; p++) {
            int idx = tid + p * 256;      // 0..511
            int m   = idx >> 2;           // 0..127
            int kq  = idx & 3;            // 0..3 (float4 group along k)
            float4 a4 = make_float4(0.f, 0.f, 0.f, 0.f);
            int gm = m0 + m;
            if (gm < N_NODES)
                a4 = *(const float4*)(A + (size_t)gm * TEXT_DIM + k0 + kq * 4);
            As[kq * 4 + 0][m] = a4.x;
            As[kq * 4 + 1][m] = a4.y;
            As[kq * 4 + 2][m] = a4.z;
            As[kq * 4 + 3][m] = a4.w;
        }
        // Load B tile: 16 k x 64 n (256 float4, 1 per thread)
        {
            int k  = tid >> 4;
            int nq = tid & 15;
            float4 b4 = *(const float4*)(W + (size_t)(k0 + k) * 64 + nq * 4);
            *(float4*)&Bs[k][nq * 4] = b4;
        }
        __syncthreads();

        #pragma unroll
        for (int k = 0; k < 16; k++) {
            float a[8], b[4];
            #pragma unroll
            for (int i = 0; i < 8; i++) a[i] = As[k][tr * 8 + i];
            #pragma unroll
            for (int j = 0; j < 4; j++) b[j] = Bs[k][tc * 4 + j];
            #pragma unroll
            for (int i = 0; i < 8; i++)
                #pragma unroll
                for (int j = 0; j < 4; j++) acc[i][j] += a[i] * b[j];
        }
        __syncthreads();
    }

    float4 bv = *(const float4*)(bias + tc * 4);
    #pragma unroll
    for (int i = 0; i < 8; i++) {
        int gm = m0 + tr * 8 + i;
        if (gm < N_NODES) {
            float4 o;
            o.x = acc[i][0] + bv.x;
            o.y = acc[i][1] + bv.y;
            o.z = acc[i][2] + bv.z;
            o.w = acc[i][3] + bv.w;
            *(float4*)(g_text0 + (size_t)gm * 64 + tc * 4) = o;
        }
    }
}

// ---------------------------------------------------------------------------
// Fused SpMM (id + text streams share the edge list).
// One warp per edge. Lanes 0..15 handle id (16 float4 = 64 floats),
// lanes 16..31 handle text. Gather h[col], scale by val, red.add.v4 to out[row].
// layer==1: id src is (user_emb | item_emb), text src g_text0 -> dst g_*1
// layer==2: src g_*1 -> dst g_*2
// ---------------------------------------------------------------------------
__global__ void spmm_kernel(const int*   __restrict__ erow,
                            const int*   __restrict__ ecol,
                            const float* __restrict__ eval,
                            const float* __restrict__ uemb,
                            const float* __restrict__ iemb,
                            int layer, int n_edges) {
    int warp = (blockIdx.x * blockDim.x + threadIdx.x) >> 5;
    int lane = threadIdx.x & 31;
    if (warp >= n_edges) return;

    int   r = __ldg(erow + warp);
    int   c = __ldg(ecol + warp);
    float v = __ldg(eval + warp);

    const float4* src;
    float4*       dst;
    if (lane < 16) {
        const float* sb;
        if (layer == 1)
            sb = (c < NUM_USERS) ? (uemb + (size_t)c * 64)
                                 : (iemb + (size_t)(c - NUM_USERS) * 64);
        else
            sb = g_id1 + (size_t)c * 64;
        src = (const float4*)sb;
        dst = (float4*)((layer == 1 ? g_id1 : g_id2) + (size_t)r * 64);
    } else {
        src = (const float4*)((layer == 1 ? g_text0 : g_text1) + (size_t)c * 64);
        dst = (float4*)((layer == 1 ? g_text1 : g_text2) + (size_t)r * 64);
    }
    int l = lane & 15;
    float4 h = __ldg(src + l);
    float4 o = make_float4(h.x * v, h.y * v, h.z * v, h.w * v);
    asm volatile("red.global.add.v4.f32 [%0], {%1, %2, %3, %4};"
                 :: "l"(dst + l), "f"(o.x), "f"(o.y), "f"(o.z), "f"(o.w)
                 : "memory");
}

// ---------------------------------------------------------------------------
// Final fusion: layer-mean, tail amplification, gate GEMM (128x64), blend.
// 256 threads = 4 nodes x 64 dims. W_fuse cached in shared (32 KB).
// tail_mask arrives as int32 (harness serializes bool arrays as int32).
// ---------------------------------------------------------------------------
__global__ void fuse_kernel(const float* __restrict__ uemb,
                            const float* __restrict__ iemb,
                            const int*   __restrict__ tail_mask,
                            const float* __restrict__ W_fuse,
                            const float* __restrict__ b_fuse,
                            const float* __restrict__ tail_amp,
                            float* __restrict__ out) {
    __shared__ float shW[128 * 64];
    __shared__ float shin[4][128];

    const int tid = threadIdx.x;
    for (int i = tid; i < 128 * 64; i += 256) shW[i] = W_fuse[i];

    const int nloc = tid >> 6;         // 0..3
    const int d    = tid & 63;         // 0..63
    const int node = blockIdx.x * 4 + nloc;

    float idf = 0.f, tf = 0.f;
    if (node < N_NODES) {
        size_t off = (size_t)node * 64 + d;
        float h0 = (node < NUM_USERS) ? uemb[(size_t)node * 64 + d]
                                      : iemb[(size_t)(node - NUM_USERS) * 64 + d];
        idf = (h0 + g_id1[off] + g_id2[off]) * (1.f / 3.f);
        tf  = (g_text0[off] + g_text1[off] + g_text2[off]) * (1.f / 3.f);
        float ta  = tail_amp[0];
        float amp = 1.f + 1.f / (1.f + __expf(-ta));
        if (tail_mask[node] != 0) tf *= amp;
    }
    shin[nloc][d]      = idf;
    shin[nloc][64 + d] = tf;
    __syncthreads();

    if (node < N_NODES) {
        float acc = b_fuse[d];
        #pragma unroll 16
        for (int j = 0; j < 128; j++)
            acc += shin[nloc][j] * shW[j * 64 + d];
        float gate = 1.f / (1.f + __expf(-acc));
        out[(size_t)node * 64 + d] = gate * idf + (1.f - gate) * tf;
    }
}

// ---------------------------------------------------------------------------
// Launch
// Inputs (metadata order): 0 text_feats, 1 edge_row, 2 edge_col, 3 edge_val,
// 4 tail_mask (int32), 5 user_emb, 6 item_emb, 7 W_text, 8 b_text, 9 W_fuse,
// 10 b_fuse, 11 tail_amp
// ---------------------------------------------------------------------------
extern "C" void kernel_launch(void* const* d_in, const int* in_sizes, int n_in,
                              void* d_out, int out_size) {
    const float* text_feats = (const float*)d_in[0];
    const int*   edge_row   = (const int*)d_in[1];
    const int*   edge_col   = (const int*)d_in[2];
    const float* edge_val   = (const float*)d_in[3];
    const int*   tail_mask  = (const int*)d_in[4];
    const float* user_emb   = (const float*)d_in[5];
    const float* item_emb   = (const float*)d_in[6];
    const float* W_text     = (const float*)d_in[7];
    const float* b_text     = (const float*)d_in[8];
    const float* W_fuse     = (const float*)d_in[9];
    const float* b_fuse     = (const float*)d_in[10];
    const float* tail_amp   = (const float*)d_in[11];
    float*       out        = (float*)d_out;

    const int n_edges = in_sizes[1];

    // 1. zero scatter destinations
    {
        int n4 = N64 / 4;
        zero_kernel<<<(n4 + 255) / 256, 256>>>();
    }
    // 2. text projection GEMM
    gemm_text_kernel<<<(N_NODES + 127) / 128, 256>>>(text_feats, W_text, b_text);
    // 3. propagation layer 1 (fused id+text spmm)
    {
        long long threads = (long long)n_edges * 32;
        int blocks = (int)((threads + 255) / 256);
        spmm_kernel<<<blocks, 256>>>(edge_row, edge_col, edge_val,
                                     user_emb, item_emb, 1, n_edges);
        // 4. propagation layer 2
        spmm_kernel<<<blocks, 256>>>(edge_row, edge_col, edge_val,
                                     user_emb, item_emb, 2, n_edges);
    }
    // 5. fusion epilogue
    fuse_kernel<<<(N_NODES + 3) / 4, 256>>>(user_emb, item_emb, tail_mask,
                                            W_fuse, b_fuse, tail_amp, out);
}

// round 3
// speedup vs baseline: 1.9106x; 1.9106x over previous
#include <cuda_runtime.h>
#include <cuda_bf16.h>
#include <cstdint>

#define NUM_USERS 100000
#define NUM_ITEMS 50000
#define N_NODES   150000
#define EMB_DIM   64
#define TEXT_DIM  384
#define N64 (N_NODES * EMB_DIM)   // 9,600,000 floats per buffer

// Scratch (device globals — allocation is prohibited)
__device__ float g_id0[N64];    // concat(user_emb, item_emb)
__device__ float g_text0[N64];  // text_feats @ W_text + b
__device__ float g_id1[N64];
__device__ float g_text1[N64];
__device__ float g_id2[N64];
__device__ float g_text2[N64];

// ---------------------------------------------------------------------------
// Prep: build g_id0 = concat(user,item); zero the 4 scatter destinations.
// ---------------------------------------------------------------------------
__global__ void prep_kernel(const float* __restrict__ uemb,
                            const float* __restrict__ iemb) {
    int i = blockIdx.x * blockDim.x + threadIdx.x;
    const int n4 = N64 / 4;
    const int u4 = NUM_USERS * (EMB_DIM / 4);
    if (i < n4) {
        float4 z = make_float4(0.f, 0.f, 0.f, 0.f);
        ((float4*)g_id1)[i]   = z;
        ((float4*)g_text1)[i] = z;
        ((float4*)g_id2)[i]   = z;
        ((float4*)g_text2)[i] = z;
        float4 src = (i < u4) ? ((const float4*)uemb)[i]
                              : ((const float4*)iemb)[i - u4];
        ((float4*)g_id0)[i] = src;
    }
}

// ---------------------------------------------------------------------------
// Text projection GEMM: g_text0[N,64] = text_feats[N,384] @ W[384,64] + b
// BM=128, BN=64, BK=16, 256 threads, 8x4 micro-tile.
// ---------------------------------------------------------------------------
__global__ void gemm_text_kernel(const float* __restrict__ A,
                                 const float* __restrict__ W,
                                 const float* __restrict__ bias) {
    __shared__ float As[16][132];   // k-major, padded
    __shared__ float Bs[16][64];

    const int tid = threadIdx.x;
    const int m0  = blockIdx.x * 128;
    const int tr  = tid >> 4;       // 0..15 -> rows tr*8..tr*8+7
    const int tc  = tid & 15;       // 0..15 -> cols tc*4..tc*4+3

    float acc[8][4];
    #pragma unroll
    for (int i = 0; i < 8; i++)
        #pragma unroll
        for (int j = 0; j < 4; j++) acc[i][j] = 0.f;

    for (int k0 = 0; k0 < TEXT_DIM; k0 += 16) {
        #pragma unroll
        for (int p = 0; p < 2; p++) {
            int idx = tid + p * 256;      // 0..511
            int m   = idx >> 2;           // 0..127
            int kq  = idx & 3;            // float4 group along k
            float4 a4 = make_float4(0.f, 0.f, 0.f, 0.f);
            int gm = m0 + m;
            if (gm < N_NODES)
                a4 = *(const float4*)(A + (size_t)gm * TEXT_DIM + k0 + kq * 4);
            As[kq * 4 + 0][m] = a4.x;
            As[kq * 4 + 1][m] = a4.y;
            As[kq * 4 + 2][m] = a4.z;
            As[kq * 4 + 3][m] = a4.w;
        }
        {
            int k  = tid >> 4;
            int nq = tid & 15;
            float4 b4 = *(const float4*)(W + (size_t)(k0 + k) * 64 + nq * 4);
            *(float4*)&Bs[k][nq * 4] = b4;
        }
        __syncthreads();

        #pragma unroll
        for (int k = 0; k < 16; k++) {
            float4 a0 = *(const float4*)&As[k][tr * 8];
            float4 a1 = *(const float4*)&As[k][tr * 8 + 4];
            float4 b  = *(const float4*)&Bs[k][tc * 4];
            float a[8] = {a0.x, a0.y, a0.z, a0.w, a1.x, a1.y, a1.z, a1.w};
            float bb[4] = {b.x, b.y, b.z, b.w};
            #pragma unroll
            for (int i = 0; i < 8; i++)
                #pragma unroll
                for (int j = 0; j < 4; j++) acc[i][j] += a[i] * bb[j];
        }
        __syncthreads();
    }

    float4 bv = *(const float4*)(bias + tc * 4);
    #pragma unroll
    for (int i = 0; i < 8; i++) {
        int gm = m0 + tr * 8 + i;
        if (gm < N_NODES) {
            float4 o;
            o.x = acc[i][0] + bv.x;
            o.y = acc[i][1] + bv.y;
            o.z = acc[i][2] + bv.z;
            o.w = acc[i][3] + bv.w;
            *(float4*)(g_text0 + (size_t)gm * 64 + tc * 4) = o;
        }
    }
}

// ---------------------------------------------------------------------------
// Fused dual-stream SpMM, 4 edges per warp (MLP=4), branch-free stream select.
// Lanes 0..15: id stream; lanes 16..31: text stream (16 float4 each = 64 fl).
// ---------------------------------------------------------------------------
#define EPW 4   // edges per warp
__global__ void spmm_kernel(const int*   __restrict__ erow,
                            const int*   __restrict__ ecol,
                            const float* __restrict__ eval,
                            const float* __restrict__ src_id,
                            const float* __restrict__ src_tx,
                            float*       __restrict__ dst_id,
                            float*       __restrict__ dst_tx,
                            int n_edges) {
    int warp = (blockIdx.x * blockDim.x + threadIdx.x) >> 5;
    int lane = threadIdx.x & 31;
    int e0 = warp * EPW;
    if (e0 >= n_edges) return;

    const float* src = (lane < 16) ? src_id : src_tx;
    float*       dst = (lane < 16) ? dst_id : dst_tx;
    const int l = lane & 15;

    int r[EPW], c[EPW];
    float v[EPW];
    #pragma unroll
    for (int i = 0; i < EPW; i++) {
        int e = e0 + i;
        int ec = (e < n_edges) ? e : (n_edges - 1);
        r[i] = __ldg(erow + ec);
        c[i] = __ldg(ecol + ec);
        v[i] = (e < n_edges) ? __ldg(eval + ec) : 0.f;  // v=0 -> adds 0, safe
    }

    float4 h[EPW];
    #pragma unroll
    for (int i = 0; i < EPW; i++)
        h[i] = __ldg((const float4*)(src + (size_t)c[i] * 64) + l);

    #pragma unroll
    for (int i = 0; i < EPW; i++) {
        float4* d = (float4*)(dst + (size_t)r[i] * 64) + l;
        asm volatile("red.global.add.v4.f32 [%0], {%1, %2, %3, %4};"
                     :: "l"(d), "f"(h[i].x * v[i]), "f"(h[i].y * v[i]),
                        "f"(h[i].z * v[i]), "f"(h[i].w * v[i])
                     : "memory");
    }
}

// ---------------------------------------------------------------------------
// Fusion epilogue: 16 nodes per 1024-thread block (W_fuse loaded once/16 nodes)
// tail_mask arrives as int32.
// ---------------------------------------------------------------------------
__global__ __launch_bounds__(1024)
void fuse_kernel(const int*   __restrict__ tail_mask,
                 const float* __restrict__ W_fuse,
                 const float* __restrict__ b_fuse,
                 const float* __restrict__ tail_amp,
                 float* __restrict__ out) {
    __shared__ float shW[128 * 64];
    __shared__ float shin[16][128];

    const int tid = threadIdx.x;
    #pragma unroll
    for (int p = 0; p < 2; p++) {
        int i = tid + p * 1024;          // 2048 float4 total
        ((float4*)shW)[i] = ((const float4*)W_fuse)[i];
    }

    const int nloc = tid >> 6;           // 0..15
    const int d    = tid & 63;
    const int node = blockIdx.x * 16 + nloc;

    float idf = 0.f, tf = 0.f;
    if (node < N_NODES) {
        size_t off = (size_t)node * 64 + d;
        idf = (g_id0[off] + g_id1[off] + g_id2[off]) * (1.f / 3.f);
        tf  = (g_text0[off] + g_text1[off] + g_text2[off]) * (1.f / 3.f);
        float ta  = tail_amp[0];
        float amp = 1.f + 1.f / (1.f + __expf(-ta));
        if (tail_mask[node] != 0) tf *= amp;
    }
    shin[nloc][d]      = idf;
    shin[nloc][64 + d] = tf;
    __syncthreads();

    if (node < N_NODES) {
        float acc = b_fuse[d];
        #pragma unroll 8
        for (int j = 0; j < 128; j++)
            acc += shin[nloc][j] * shW[j * 64 + d];
        float gate = 1.f / (1.f + __expf(-acc));
        out[(size_t)node * 64 + d] = gate * idf + (1.f - gate) * tf;
    }
}

// ---------------------------------------------------------------------------
// Launch. Inputs: 0 text_feats, 1 edge_row, 2 edge_col, 3 edge_val,
// 4 tail_mask(int32), 5 user_emb, 6 item_emb, 7 W_text, 8 b_text,
// 9 W_fuse, 10 b_fuse, 11 tail_amp
// ---------------------------------------------------------------------------
extern "C" void kernel_launch(void* const* d_in, const int* in_sizes, int n_in,
                              void* d_out, int out_size) {
    const float* text_feats = (const float*)d_in[0];
    const int*   edge_row   = (const int*)d_in[1];
    const int*   edge_col   = (const int*)d_in[2];
    const float* edge_val   = (const float*)d_in[3];
    const int*   tail_mask  = (const int*)d_in[4];
    const float* user_emb   = (const float*)d_in[5];
    const float* item_emb   = (const float*)d_in[6];
    const float* W_text     = (const float*)d_in[7];
    const float* b_text     = (const float*)d_in[8];
    const float* W_fuse     = (const float*)d_in[9];
    const float* b_fuse     = (const float*)d_in[10];
    const float* tail_amp   = (const float*)d_in[11];
    float*       out        = (float*)d_out;

    const int n_edges = in_sizes[1];

    float *p_id0, *p_text0, *p_id1, *p_text1, *p_id2, *p_text2;
    cudaGetSymbolAddress((void**)&p_id0,   g_id0);
    cudaGetSymbolAddress((void**)&p_text0, g_text0);
    cudaGetSymbolAddress((void**)&p_id1,   g_id1);
    cudaGetSymbolAddress((void**)&p_text1, g_text1);
    cudaGetSymbolAddress((void**)&p_id2,   g_id2);
    cudaGetSymbolAddress((void**)&p_text2, g_text2);

    // 1. prep: concat id emb + zero destinations
    {
        int n4 = N64 / 4;
        prep_kernel<<<(n4 + 255) / 256, 256>>>(user_emb, item_emb);
    }
    // 2. text projection GEMM
    gemm_text_kernel<<<(N_NODES + 127) / 128, 256>>>(text_feats, W_text, b_text);
    // 3+4. propagation layers (fused id+text spmm, 4 edges/warp)
    {
        int warps  = (n_edges + EPW - 1) / EPW;
        int blocks = (warps * 32 + 255) / 256;
        spmm_kernel<<<blocks, 256>>>(edge_row, edge_col, edge_val,
                                     p_id0, p_text0, p_id1, p_text1, n_edges);
        spmm_kernel<<<blocks, 256>>>(edge_row, edge_col, edge_val,
                                     p_id1, p_text1, p_id2, p_text2, n_edges);
    }
    // 5. fusion epilogue
    fuse_kernel<<<(N_NODES + 15) / 16, 1024>>>(tail_mask, W_fuse, b_fuse,
                                               tail_amp, out);
}

// round 4
// speedup vs baseline: 2.2037x; 1.1534x over previous
#include <cuda_runtime.h>
#include <cuda_bf16.h>
#include <cstdint>

#define NUM_USERS 100000
#define NUM_ITEMS 50000
#define N_NODES   150000
#define EMB_DIM   64
#define TEXT_DIM  384
#define N64 (N_NODES * EMB_DIM)   // 9,600,000 floats per buffer
#define MAX_EDGES 5000000

// Scratch (device globals — allocation is prohibited)
__device__ float g_id0[N64];    // concat(user_emb, item_emb)
__device__ float g_text0[N64];  // text_feats @ W_text + b
__device__ float g_id1[N64];
__device__ float g_text1[N64];
__device__ float g_id2[N64];
__device__ float g_text2[N64];

// CSR machinery
__device__ int  g_cnt[N_NODES];
__device__ int  g_ofs[N_NODES + 1];
__device__ int  g_cur[N_NODES];
__device__ int2 g_edges[MAX_EDGES];   // packed (col, val-as-int), row-sorted

// ---------------------------------------------------------------------------
// Prep: g_id0 = concat(user,item); zero row-count histogram.
// ---------------------------------------------------------------------------
__global__ void prep_kernel(const float* __restrict__ uemb,
                            const float* __restrict__ iemb) {
    int i = blockIdx.x * blockDim.x + threadIdx.x;
    const int n4 = N64 / 4;
    const int u4 = NUM_USERS * (EMB_DIM / 4);
    if (i < n4) {
        float4 src = (i < u4) ? ((const float4*)uemb)[i]
                              : ((const float4*)iemb)[i - u4];
        ((float4*)g_id0)[i] = src;
    }
    if (i < N_NODES / 4)   // 150000 % 4 == 0
        ((int4*)g_cnt)[i] = make_int4(0, 0, 0, 0);
}

// ---------------------------------------------------------------------------
// Histogram of edge rows
// ---------------------------------------------------------------------------
__global__ void hist_kernel(const int* __restrict__ erow, int n_edges) {
    int i = blockIdx.x * blockDim.x + threadIdx.x;
    if (i < n_edges) atomicAdd(&g_cnt[__ldg(erow + i)], 1);
}

// ---------------------------------------------------------------------------
// Exclusive scan over g_cnt -> g_ofs (+ cursor copy). Single block, 1024 thr.
// ---------------------------------------------------------------------------
__global__ __launch_bounds__(1024)
void scan_kernel() {
    __shared__ int sdata[1024];
    const int t = threadIdx.x;
    const int CHUNK = (N_NODES + 1023) / 1024;   // 147
    int begin = t * CHUNK;
    int end   = begin + CHUNK; if (end > N_NODES) end = N_NODES;
    int s = 0;
    for (int i = begin; i < end && i < N_NODES; i++) s += g_cnt[i];
    sdata[t] = s;
    __syncthreads();
    // Hillis-Steele inclusive scan
    for (int off = 1; off < 1024; off <<= 1) {
        int v = (t >= off) ? sdata[t - off] : 0;
        __syncthreads();
        sdata[t] += v;
        __syncthreads();
    }
    int run = sdata[t] - s;   // exclusive prefix
    for (int i = begin; i < end && i < N_NODES; i++) {
        int c = g_cnt[i];
        g_ofs[i] = run;
        g_cur[i] = run;
        run += c;
    }
    if (t == 1023) g_ofs[N_NODES] = sdata[1023];
}

// ---------------------------------------------------------------------------
// Scatter edges into row-sorted packed array
// ---------------------------------------------------------------------------
__global__ void scatter_kernel(const int*   __restrict__ erow,
                               const int*   __restrict__ ecol,
                               const float* __restrict__ eval,
                               int n_edges) {
    int i = blockIdx.x * blockDim.x + threadIdx.x;
    if (i < n_edges) {
        int r = __ldg(erow + i);
        int pos = atomicAdd(&g_cur[r], 1);
        g_edges[pos] = make_int2(__ldg(ecol + i),
                                 __float_as_int(__ldg(eval + i)));
    }
}

// ---------------------------------------------------------------------------
// Text projection GEMM: g_text0[N,64] = text_feats[N,384] @ W[384,64] + b
// ---------------------------------------------------------------------------
__global__ void gemm_text_kernel(const float* __restrict__ A,
                                 const float* __restrict__ W,
                                 const float* __restrict__ bias) {
    __shared__ float As[16][132];   // k-major, padded
    __shared__ float Bs[16][64];

    const int tid = threadIdx.x;
    const int m0  = blockIdx.x * 128;
    const int tr  = tid >> 4;
    const int tc  = tid & 15;

    float acc[8][4];
    #pragma unroll
    for (int i = 0; i < 8; i++)
        #pragma unroll
        for (int j = 0; j < 4; j++) acc[i][j] = 0.f;

    for (int k0 = 0; k0 < TEXT_DIM; k0 += 16) {
        #pragma unroll
        for (int p = 0; p < 2; p++) {
            int idx = tid + p * 256;
            int m   = idx >> 2;
            int kq  = idx & 3;
            float4 a4 = make_float4(0.f, 0.f, 0.f, 0.f);
            int gm = m0 + m;
            if (gm < N_NODES)
                a4 = *(const float4*)(A + (size_t)gm * TEXT_DIM + k0 + kq * 4);
            As[kq * 4 + 0][m] = a4.x;
            As[kq * 4 + 1][m] = a4.y;
            As[kq * 4 + 2][m] = a4.z;
            As[kq * 4 + 3][m] = a4.w;
        }
        {
            int k  = tid >> 4;
            int nq = tid & 15;
            float4 b4 = *(const float4*)(W + (size_t)(k0 + k) * 64 + nq * 4);
            *(float4*)&Bs[k][nq * 4] = b4;
        }
        __syncthreads();

        #pragma unroll
        for (int k = 0; k < 16; k++) {
            float4 a0 = *(const float4*)&As[k][tr * 8];
            float4 a1 = *(const float4*)&As[k][tr * 8 + 4];
            float4 b  = *(const float4*)&Bs[k][tc * 4];
            float a[8] = {a0.x, a0.y, a0.z, a0.w, a1.x, a1.y, a1.z, a1.w};
            float bb[4] = {b.x, b.y, b.z, b.w};
            #pragma unroll
            for (int i = 0; i < 8; i++)
                #pragma unroll
                for (int j = 0; j < 4; j++) acc[i][j] += a[i] * bb[j];
        }
        __syncthreads();
    }

    float4 bv = *(const float4*)(bias + tc * 4);
    #pragma unroll
    for (int i = 0; i < 8; i++) {
        int gm = m0 + tr * 8 + i;
        if (gm < N_NODES) {
            float4 o;
            o.x = acc[i][0] + bv.x;
            o.y = acc[i][1] + bv.y;
            o.z = acc[i][2] + bv.z;
            o.w = acc[i][3] + bv.w;
            *(float4*)(g_text0 + (size_t)gm * 64 + tc * 4) = o;
        }
    }
}

// ---------------------------------------------------------------------------
// CSR SpMM, atomic-free. One warp per (row, stream); float2 per lane.
// Edge loop unrolled x4 for MLP. Adjacent warps share a row -> edge data hot.
// ---------------------------------------------------------------------------
__global__ void spmm_csr_kernel(const float* __restrict__ src_id,
                                const float* __restrict__ src_tx,
                                float*       __restrict__ dst_id,
                                float*       __restrict__ dst_tx) {
    int gw   = (blockIdx.x * blockDim.x + threadIdx.x) >> 5;
    int lane = threadIdx.x & 31;
    int row  = gw >> 1;
    if (row >= N_NODES) return;

    const float* src = (gw & 1) ? src_tx : src_id;
    float*       dst = (gw & 1) ? dst_tx : dst_id;

    int beg = __ldg(&g_ofs[row]);
    int end = __ldg(&g_ofs[row + 1]);

    float2 acc = make_float2(0.f, 0.f);
    int e = beg;
    for (; e + 4 <= end; e += 4) {
        int2 d0 = __ldg(&g_edges[e + 0]);
        int2 d1 = __ldg(&g_edges[e + 1]);
        int2 d2 = __ldg(&g_edges[e + 2]);
        int2 d3 = __ldg(&g_edges[e + 3]);
        float2 h0 = __ldg((const float2*)(src + (size_t)d0.x * 64) + lane);
        float2 h1 = __ldg((const float2*)(src + (size_t)d1.x * 64) + lane);
        float2 h2 = __ldg((const float2*)(src + (size_t)d2.x * 64) + lane);
        float2 h3 = __ldg((const float2*)(src + (size_t)d3.x * 64) + lane);
        float v0 = __int_as_float(d0.y), v1 = __int_as_float(d1.y);
        float v2 = __int_as_float(d2.y), v3 = __int_as_float(d3.y);
        acc.x += h0.x * v0; acc.y += h0.y * v0;
        acc.x += h1.x * v1; acc.y += h1.y * v1;
        acc.x += h2.x * v2; acc.y += h2.y * v2;
        acc.x += h3.x * v3; acc.y += h3.y * v3;
    }
    for (; e < end; e++) {
        int2 d = __ldg(&g_edges[e]);
        float2 h = __ldg((const float2*)(src + (size_t)d.x * 64) + lane);
        float v = __int_as_float(d.y);
        acc.x += h.x * v; acc.y += h.y * v;
    }
    ((float2*)(dst + (size_t)row * 64))[lane] = acc;
}

// ---------------------------------------------------------------------------
// Fusion epilogue: 16 nodes per 1024-thread block. tail_mask is int32.
// ---------------------------------------------------------------------------
__global__ __launch_bounds__(1024)
void fuse_kernel(const int*   __restrict__ tail_mask,
                 const float* __restrict__ W_fuse,
                 const float* __restrict__ b_fuse,
                 const float* __restrict__ tail_amp,
                 float* __restrict__ out) {
    __shared__ float shW[128 * 64];
    __shared__ float shin[16][128];

    const int tid = threadIdx.x;
    #pragma unroll
    for (int p = 0; p < 2; p++) {
        int i = tid + p * 1024;
        ((float4*)shW)[i] = ((const float4*)W_fuse)[i];
    }

    const int nloc = tid >> 6;
    const int d    = tid & 63;
    const int node = blockIdx.x * 16 + nloc;

    float idf = 0.f, tf = 0.f;
    if (node < N_NODES) {
        size_t off = (size_t)node * 64 + d;
        idf = (g_id0[off] + g_id1[off] + g_id2[off]) * (1.f / 3.f);
        tf  = (g_text0[off] + g_text1[off] + g_text2[off]) * (1.f / 3.f);
        float ta  = tail_amp[0];
        float amp = 1.f + 1.f / (1.f + __expf(-ta));
        if (tail_mask[node] != 0) tf *= amp;
    }
    shin[nloc][d]      = idf;
    shin[nloc][64 + d] = tf;
    __syncthreads();

    if (node < N_NODES) {
        float acc = b_fuse[d];
        #pragma unroll 8
        for (int j = 0; j < 128; j++)
            acc += shin[nloc][j] * shW[j * 64 + d];
        float gate = 1.f / (1.f + __expf(-acc));
        out[(size_t)node * 64 + d] = gate * idf + (1.f - gate) * tf;
    }
}

// ---------------------------------------------------------------------------
// Launch. Inputs: 0 text_feats, 1 edge_row, 2 edge_col, 3 edge_val,
// 4 tail_mask(int32), 5 user_emb, 6 item_emb, 7 W_text, 8 b_text,
// 9 W_fuse, 10 b_fuse, 11 tail_amp
// ---------------------------------------------------------------------------
extern "C" void kernel_launch(void* const* d_in, const int* in_sizes, int n_in,
                              void* d_out, int out_size) {
    const float* text_feats = (const float*)d_in[0];
    const int*   edge_row   = (const int*)d_in[1];
    const int*   edge_col   = (const int*)d_in[2];
    const float* edge_val   = (const float*)d_in[3];
    const int*   tail_mask  = (const int*)d_in[4];
    const float* user_emb   = (const float*)d_in[5];
    const float* item_emb   = (const float*)d_in[6];
    const float* W_text     = (const float*)d_in[7];
    const float* b_text     = (const float*)d_in[8];
    const float* W_fuse     = (const float*)d_in[9];
    const float* b_fuse     = (const float*)d_in[10];
    const float* tail_amp   = (const float*)d_in[11];
    float*       out        = (float*)d_out;

    const int n_edges = in_sizes[1];

    float *p_id0, *p_text0, *p_id1, *p_text1, *p_id2, *p_text2;
    cudaGetSymbolAddress((void**)&p_id0,   g_id0);
    cudaGetSymbolAddress((void**)&p_text0, g_text0);
    cudaGetSymbolAddress((void**)&p_id1,   g_id1);
    cudaGetSymbolAddress((void**)&p_text1, g_text1);
    cudaGetSymbolAddress((void**)&p_id2,   g_id2);
    cudaGetSymbolAddress((void**)&p_text2, g_text2);

    // 1. prep: concat id emb + zero histogram
    {
        int n4 = N64 / 4;
        prep_kernel<<<(n4 + 255) / 256, 256>>>(user_emb, item_emb);
    }
    // 2. CSR build: histogram -> scan -> scatter
    hist_kernel<<<(n_edges + 255) / 256, 256>>>(edge_row, n_edges);
    scan_kernel<<<1, 1024>>>();
    scatter_kernel<<<(n_edges + 255) / 256, 256>>>(edge_row, edge_col,
                                                   edge_val, n_edges);
    // 3. text projection GEMM
    gemm_text_kernel<<<(N_NODES + 127) / 128, 256>>>(text_feats, W_text, b_text);
    // 4+5. propagation layers (CSR, atomic-free)
    {
        int warps  = 2 * N_NODES;
        int blocks = (warps * 32 + 255) / 256;
        spmm_csr_kernel<<<blocks, 256>>>(p_id0, p_text0, p_id1, p_text1);
        spmm_csr_kernel<<<blocks, 256>>>(p_id1, p_text1, p_id2, p_text2);
    }
    // 6. fusion epilogue
    fuse_kernel<<<(N_NODES + 15) / 16, 1024>>>(tail_mask, W_fuse, b_fuse,
                                               tail_amp, out);
}

// round 5
// speedup vs baseline: 2.6485x; 1.2018x over previous
#include <cuda_runtime.h>
#include <cuda_bf16.h>
#include <cuda_fp16.h>
#include <cstdint>

#define NUM_USERS 100000
#define NUM_ITEMS 50000
#define N_NODES   150000
#define EMB_DIM   64
#define TEXT_DIM  384
#define N64 (N_NODES * EMB_DIM)   // 9,600,000 floats per buffer
#define MAX_EDGES 5000000

// fp32 scratch (device globals — allocation is prohibited)
__device__ float g_id0[N64];    // concat(user_emb, item_emb), exact
__device__ float g_text0[N64];  // text_feats @ W_text + b, exact
__device__ float g_id1[N64];    // fp32 layer outputs (for fusion sums)
__device__ float g_text1[N64];
__device__ float g_id2[N64];
__device__ float g_text2[N64];

// fp16 interleaved gather buffers: per node 64 words (unsigned), word layout:
//   word[node*64 + 2*l + 0] = half2(id[2l],  id[2l+1])
//   word[node*64 + 2*l + 1] = half2(tx[2l],  tx[2l+1])
// so lane l gathers ONE uint2 (8 B) covering both streams.
__device__ unsigned g_b0[N_NODES * 64];
__device__ unsigned g_b1[N_NODES * 64];

// CSR machinery
__device__ int  g_cnt[N_NODES];
__device__ int  g_ofs[N_NODES + 1];
__device__ int  g_cur[N_NODES];
__device__ int2 g_edges[MAX_EDGES];   // (col, val bits), row-sorted

static __device__ __forceinline__ unsigned pack_h2(float a, float b) {
    __half2 h = __floats2half2_rn(a, b);
    return *reinterpret_cast<unsigned*>(&h);
}

// ---------------------------------------------------------------------------
// Prep: g_id0 = concat(user,item) fp32; fp16 id words of g_b0; zero histogram.
// Thread i handles float4 i of the concat buffer -> words 4i, 4i+2 of g_b0.
// ---------------------------------------------------------------------------
__global__ void prep_kernel(const float* __restrict__ uemb,
                            const float* __restrict__ iemb) {
    int i = blockIdx.x * blockDim.x + threadIdx.x;
    const int n4 = N64 / 4;
    const int u4 = NUM_USERS * (EMB_DIM / 4);
    if (i < n4) {
        float4 src = (i < u4) ? ((const float4*)uemb)[i]
                              : ((const float4*)iemb)[i - u4];
        ((float4*)g_id0)[i] = src;
        g_b0[4 * i]     = pack_h2(src.x, src.y);
        g_b0[4 * i + 2] = pack_h2(src.z, src.w);
    }
    if (i < N_NODES / 4)
        ((int4*)g_cnt)[i] = make_int4(0, 0, 0, 0);
}

// ---------------------------------------------------------------------------
// CSR build: histogram, single-block scan, scatter
// ---------------------------------------------------------------------------
__global__ void hist_kernel(const int* __restrict__ erow, int n_edges) {
    int i = blockIdx.x * blockDim.x + threadIdx.x;
    if (i < n_edges) atomicAdd(&g_cnt[__ldg(erow + i)], 1);
}

__global__ __launch_bounds__(1024)
void scan_kernel() {
    __shared__ int sdata[1024];
    const int t = threadIdx.x;
    const int CHUNK = (N_NODES + 1023) / 1024;   // 147
    int begin = t * CHUNK;
    int end   = begin + CHUNK; if (end > N_NODES) end = N_NODES;
    int s = 0;
    for (int i = begin; i < end; i++) s += g_cnt[i];
    sdata[t] = s;
    __syncthreads();
    for (int off = 1; off < 1024; off <<= 1) {
        int v = (t >= off) ? sdata[t - off] : 0;
        __syncthreads();
        sdata[t] += v;
        __syncthreads();
    }
    int run = sdata[t] - s;
    for (int i = begin; i < end; i++) {
        int c = g_cnt[i];
        g_ofs[i] = run;
        g_cur[i] = run;
        run += c;
    }
    if (t == 1023) g_ofs[N_NODES] = sdata[1023];
}

__global__ void scatter_kernel(const int*   __restrict__ erow,
                               const int*   __restrict__ ecol,
                               const float* __restrict__ eval,
                               int n_edges) {
    int i = blockIdx.x * blockDim.x + threadIdx.x;
    if (i < n_edges) {
        int r = __ldg(erow + i);
        int pos = atomicAdd(&g_cur[r], 1);
        g_edges[pos] = make_int2(__ldg(ecol + i),
                                 __float_as_int(__ldg(eval + i)));
    }
}

// ---------------------------------------------------------------------------
// Text GEMM with packed f32x2 FFMA. Writes fp32 g_text0 + fp16 text words.
// BM=128, BN=64, BK=16, 256 threads, 8x4 micro-tile (rows packed in pairs).
// ---------------------------------------------------------------------------
__global__ void gemm_text_kernel(const float* __restrict__ A,
                                 const float* __restrict__ W,
                                 const float* __restrict__ bias) {
    __shared__ float As[16][132];   // k-major, padded, row start 16B-aligned
    __shared__ float Bs[16][64];

    const int tid = threadIdx.x;
    const int m0  = blockIdx.x * 128;
    const int tr  = tid >> 4;       // rows tr*8..tr*8+7
    const int tc  = tid & 15;       // cols tc*4..tc*4+3

    // acc2[ip][j] packs rows (tr*8+2ip, tr*8+2ip+1) for column tc*4+j
    unsigned long long acc2[4][4];
    #pragma unroll
    for (int ip = 0; ip < 4; ip++)
        #pragma unroll
        for (int j = 0; j < 4; j++) acc2[ip][j] = 0ull;

    for (int k0 = 0; k0 < TEXT_DIM; k0 += 16) {
        #pragma unroll
        for (int p = 0; p < 2; p++) {
            int idx = tid + p * 256;
            int m   = idx >> 2;
            int kq  = idx & 3;
            float4 a4 = make_float4(0.f, 0.f, 0.f, 0.f);
            int gm = m0 + m;
            if (gm < N_NODES)
                a4 = *(const float4*)(A + (size_t)gm * TEXT_DIM + k0 + kq * 4);
            As[kq * 4 + 0][m] = a4.x;
            As[kq * 4 + 1][m] = a4.y;
            As[kq * 4 + 2][m] = a4.z;
            As[kq * 4 + 3][m] = a4.w;
        }
        {
            int k  = tid >> 4;
            int nq = tid & 15;
            float4 b4 = *(const float4*)(W + (size_t)(k0 + k) * 64 + nq * 4);
            *(float4*)&Bs[k][nq * 4] = b4;
        }
        __syncthreads();

        #pragma unroll
        for (int k = 0; k < 16; k++) {
            const unsigned long long* pa =
                (const unsigned long long*)&As[k][tr * 8];
            unsigned long long av[4] = {pa[0], pa[1], pa[2], pa[3]};
            float4 b = *(const float4*)&Bs[k][tc * 4];
            unsigned long long bd[4];
            asm("mov.b64 %0, {%1, %1};" : "=l"(bd[0]) : "r"(__float_as_uint(b.x)));
            asm("mov.b64 %0, {%1, %1};" : "=l"(bd[1]) : "r"(__float_as_uint(b.y)));
            asm("mov.b64 %0, {%1, %1};" : "=l"(bd[2]) : "r"(__float_as_uint(b.z)));
            asm("mov.b64 %0, {%1, %1};" : "=l"(bd[3]) : "r"(__float_as_uint(b.w)));
            #pragma unroll
            for (int ip = 0; ip < 4; ip++)
                #pragma unroll
                for (int j = 0; j < 4; j++)
                    asm("fma.rn.f32x2 %0, %1, %2, %3;"
                        : "=l"(acc2[ip][j])
                        : "l"(av[ip]), "l"(bd[j]), "l"(acc2[ip][j]));
        }
        __syncthreads();
    }

    float4 bv = *(const float4*)(bias + tc * 4);
    #pragma unroll
    for (int ip = 0; ip < 4; ip++) {
        float2 lo_hi[4];
        #pragma unroll
        for (int j = 0; j < 4; j++)
            lo_hi[j] = *reinterpret_cast<float2*>(&acc2[ip][j]);
        #pragma unroll
        for (int half = 0; half < 2; half++) {
            int gm = m0 + tr * 8 + 2 * ip + half;
            if (gm < N_NODES) {
                float4 o;
                o.x = (half ? lo_hi[0].y : lo_hi[0].x) + bv.x;
                o.y = (half ? lo_hi[1].y : lo_hi[1].x) + bv.y;
                o.z = (half ? lo_hi[2].y : lo_hi[2].x) + bv.z;
                o.w = (half ? lo_hi[3].y : lo_hi[3].x) + bv.w;
                *(float4*)(g_text0 + (size_t)gm * 64 + tc * 4) = o;
                // fp16 text words: word index gm*64 + 4*tc + 1 / + 3
                g_b0[(size_t)gm * 64 + 4 * tc + 1] = pack_h2(o.x, o.y);
                g_b0[(size_t)gm * 64 + 4 * tc + 3] = pack_h2(o.z, o.w);
            }
        }
    }
}

// ---------------------------------------------------------------------------
// CSR SpMM, fp16 gather, both streams per warp. One warp per row.
// Per edge per lane: one LDG.64 (id half2 + text half2). fp32 accumulate.
// Writes fp32 layer outputs (+ fp16 words for the next layer if dst_b != 0).
// ---------------------------------------------------------------------------
__global__ void spmm_csr_kernel(const unsigned* __restrict__ src_b,
                                float*    __restrict__ dst_id,
                                float*    __restrict__ dst_tx,
                                unsigned* __restrict__ dst_b) {
    int row  = (blockIdx.x * blockDim.x + threadIdx.x) >> 5;
    int lane = threadIdx.x & 31;
    if (row >= N_NODES) return;

    int beg = __ldg(&g_ofs[row]);
    int end = __ldg(&g_ofs[row + 1]);

    const uint2* src = (const uint2*)src_b;   // index: col*32 + lane

    float2 aid = make_float2(0.f, 0.f);
    float2 atx = make_float2(0.f, 0.f);

    int e = beg;
    for (; e + 4 <= end; e += 4) {
        int2 d0 = __ldg(&g_edges[e + 0]);
        int2 d1 = __ldg(&g_edges[e + 1]);
        int2 d2 = __ldg(&g_edges[e + 2]);
        int2 d3 = __ldg(&g_edges[e + 3]);
        uint2 w0 = __ldg(src + (size_t)d0.x * 32 + lane);
        uint2 w1 = __ldg(src + (size_t)d1.x * 32 + lane);
        uint2 w2 = __ldg(src + (size_t)d2.x * 32 + lane);
        uint2 w3 = __ldg(src + (size_t)d3.x * 32 + lane);
        float v0 = __int_as_float(d0.y), v1 = __int_as_float(d1.y);
        float v2 = __int_as_float(d2.y), v3 = __int_as_float(d3.y);
        float2 f;
        f = __half22float2(*reinterpret_cast<__half2*>(&w0.x)); aid.x += f.x * v0; aid.y += f.y * v0;
        f = __half22float2(*reinterpret_cast<__half2*>(&w0.y)); atx.x += f.x * v0; atx.y += f.y * v0;
        f = __half22float2(*reinterpret_cast<__half2*>(&w1.x)); aid.x += f.x * v1; aid.y += f.y * v1;
        f = __half22float2(*reinterpret_cast<__half2*>(&w1.y)); atx.x += f.x * v1; atx.y += f.y * v1;
        f = __half22float2(*reinterpret_cast<__half2*>(&w2.x)); aid.x += f.x * v2; aid.y += f.y * v2;
        f = __half22float2(*reinterpret_cast<__half2*>(&w2.y)); atx.x += f.x * v2; atx.y += f.y * v2;
        f = __half22float2(*reinterpret_cast<__half2*>(&w3.x)); aid.x += f.x * v3; aid.y += f.y * v3;
        f = __half22float2(*reinterpret_cast<__half2*>(&w3.y)); atx.x += f.x * v3; atx.y += f.y * v3;
    }
    for (; e < end; e++) {
        int2 d = __ldg(&g_edges[e]);
        uint2 w = __ldg(src + (size_t)d.x * 32 + lane);
        float v = __int_as_float(d.y);
        float2 f;
        f = __half22float2(*reinterpret_cast<__half2*>(&w.x)); aid.x += f.x * v; aid.y += f.y * v;
        f = __half22float2(*reinterpret_cast<__half2*>(&w.y)); atx.x += f.x * v; atx.y += f.y * v;
    }

    size_t o = (size_t)row * 64 + 2 * lane;
    *(float2*)(dst_id + o) = aid;
    *(float2*)(dst_tx + o) = atx;
    if (dst_b) {
        uint2 w;
        w.x = pack_h2(aid.x, aid.y);
        w.y = pack_h2(atx.x, atx.y);
        ((uint2*)dst_b)[(size_t)row * 32 + lane] = w;
    }
}

// ---------------------------------------------------------------------------
// Fusion epilogue: 16 nodes per 1024-thread block. tail_mask is int32.
// ---------------------------------------------------------------------------
__global__ __launch_bounds__(1024)
void fuse_kernel(const int*   __restrict__ tail_mask,
                 const float* __restrict__ W_fuse,
                 const float* __restrict__ b_fuse,
                 const float* __restrict__ tail_amp,
                 float* __restrict__ out) {
    __shared__ float shW[128 * 64];
    __shared__ float shin[16][128];

    const int tid = threadIdx.x;
    #pragma unroll
    for (int p = 0; p < 2; p++) {
        int i = tid + p * 1024;
        ((float4*)shW)[i] = ((const float4*)W_fuse)[i];
    }

    const int nloc = tid >> 6;
    const int d    = tid & 63;
    const int node = blockIdx.x * 16 + nloc;

    float idf = 0.f, tf = 0.f;
    if (node < N_NODES) {
        size_t off = (size_t)node * 64 + d;
        idf = (g_id0[off] + g_id1[off] + g_id2[off]) * (1.f / 3.f);
        tf  = (g_text0[off] + g_text1[off] + g_text2[off]) * (1.f / 3.f);
        float ta  = tail_amp[0];
        float amp = 1.f + 1.f / (1.f + __expf(-ta));
        if (tail_mask[node] != 0) tf *= amp;
    }
    shin[nloc][d]      = idf;
    shin[nloc][64 + d] = tf;
    __syncthreads();

    if (node < N_NODES) {
        float acc = b_fuse[d];
        #pragma unroll 8
        for (int j = 0; j < 128; j++)
            acc += shin[nloc][j] * shW[j * 64 + d];
        float gate = 1.f / (1.f + __expf(-acc));
        out[(size_t)node * 64 + d] = gate * idf + (1.f - gate) * tf;
    }
}

// ---------------------------------------------------------------------------
// Launch. Inputs: 0 text_feats, 1 edge_row, 2 edge_col, 3 edge_val,
// 4 tail_mask(int32), 5 user_emb, 6 item_emb, 7 W_text, 8 b_text,
// 9 W_fuse, 10 b_fuse, 11 tail_amp
// ---------------------------------------------------------------------------
extern "C" void kernel_launch(void* const* d_in, const int* in_sizes, int n_in,
                              void* d_out, int out_size) {
    const float* text_feats = (const float*)d_in[0];
    const int*   edge_row   = (const int*)d_in[1];
    const int*   edge_col   = (const int*)d_in[2];
    const float* edge_val   = (const float*)d_in[3];
    const int*   tail_mask  = (const int*)d_in[4];
    const float* user_emb   = (const float*)d_in[5];
    const float* item_emb   = (const float*)d_in[6];
    const float* W_text     = (const float*)d_in[7];
    const float* b_text     = (const float*)d_in[8];
    const float* W_fuse     = (const float*)d_in[9];
    const float* b_fuse     = (const float*)d_in[10];
    const float* tail_amp   = (const float*)d_in[11];
    float*       out        = (float*)d_out;

    const int n_edges = in_sizes[1];

    float *p_id1, *p_text1, *p_id2, *p_text2;
    unsigned *p_b0, *p_b1;
    cudaGetSymbolAddress((void**)&p_id1,   g_id1);
    cudaGetSymbolAddress((void**)&p_text1, g_text1);
    cudaGetSymbolAddress((void**)&p_id2,   g_id2);
    cudaGetSymbolAddress((void**)&p_text2, g_text2);
    cudaGetSymbolAddress((void**)&p_b0,    g_b0);
    cudaGetSymbolAddress((void**)&p_b1,    g_b1);

    // 1. prep: concat id emb (fp32 + fp16 words) + zero histogram
    {
        int n4 = N64 / 4;
        prep_kernel<<<(n4 + 255) / 256, 256>>>(user_emb, item_emb);
    }
    // 2. CSR build
    hist_kernel<<<(n_edges + 255) / 256, 256>>>(edge_row, n_edges);
    scan_kernel<<<1, 1024>>>();
    scatter_kernel<<<(n_edges + 255) / 256, 256>>>(edge_row, edge_col,
                                                   edge_val, n_edges);
    // 3. text GEMM (fp32 out + fp16 words)
    gemm_text_kernel<<<(N_NODES + 127) / 128, 256>>>(text_feats, W_text, b_text);
    // 4+5. propagation (fp16 gather, both streams per warp)
    {
        int blocks = (N_NODES * 32 + 255) / 256;
        spmm_csr_kernel<<<blocks, 256>>>(p_b0, p_id1, p_text1, p_b1);
        spmm_csr_kernel<<<blocks, 256>>>(p_b1, p_id2, p_text2, nullptr);
    }
    // 6. fusion epilogue
    fuse_kernel<<<(N_NODES + 15) / 16, 1024>>>(tail_mask, W_fuse, b_fuse,
                                               tail_amp, out);
}

// round 6
// speedup vs baseline: 3.1676x; 1.1960x over previous
#include <cuda_runtime.h>
#include <cuda_bf16.h>
#include <cuda_fp16.h>
#include <cstdint>

#define NUM_USERS 100000
#define NUM_ITEMS 50000
#define N_NODES   150000
#define EMB_DIM   64
#define TEXT_DIM  384
#define N64 (N_NODES * EMB_DIM)
#define MAX_EDGES 5000000

// fp32 text projection (exact, used in fusion sums)
__device__ float g_text0[N64];

// fp16 interleaved buffers: per node 64 uint words.
//   word[node*64 + 2*p + 0] = half2(id[2p], id[2p+1])
//   word[node*64 + 2*p + 1] = half2(tx[2p], tx[2p+1])
// lane l of a gather warp loads uint2 at (uint2*)buf + node*32 + l.
__device__ unsigned g_b0[N_NODES * 64];
__device__ unsigned g_b1[N_NODES * 64];
__device__ unsigned g_b2[N_NODES * 64];

// CSR machinery
__device__ int  g_cnt[N_NODES];
__device__ int  g_ofs[N_NODES + 1];
__device__ int  g_cur[N_NODES];
__device__ int2 g_edges[MAX_EDGES];   // (col, val bits), row-sorted

static __device__ __forceinline__ unsigned pack_h2(float a, float b) {
    __half2 h = __floats2half2_rn(a, b);
    return *reinterpret_cast<unsigned*>(&h);
}
static __device__ __forceinline__ float2 unpack_h2(unsigned w) {
    return __half22float2(*reinterpret_cast<__half2*>(&w));
}

// ---------------------------------------------------------------------------
// Prep: fp16 id words of g_b0 from concat(uemb,iemb); zero histogram.
// Thread i handles float4 i of the logical concat -> words 4i, 4i+2.
// ---------------------------------------------------------------------------
__global__ void prep_kernel(const float* __restrict__ uemb,
                            const float* __restrict__ iemb) {
    int i = blockIdx.x * blockDim.x + threadIdx.x;
    const int n4 = N64 / 4;
    const int u4 = NUM_USERS * (EMB_DIM / 4);
    if (i < n4) {
        float4 src = (i < u4) ? ((const float4*)uemb)[i]
                              : ((const float4*)iemb)[i - u4];
        g_b0[4 * i]     = pack_h2(src.x, src.y);
        g_b0[4 * i + 2] = pack_h2(src.z, src.w);
    }
    if (i < N_NODES / 4)
        ((int4*)g_cnt)[i] = make_int4(0, 0, 0, 0);
}

// ---------------------------------------------------------------------------
// CSR build: histogram, single-block scan, scatter
// ---------------------------------------------------------------------------
__global__ void hist_kernel(const int* __restrict__ erow, int n_edges) {
    int i = blockIdx.x * blockDim.x + threadIdx.x;
    if (i < n_edges) atomicAdd(&g_cnt[__ldg(erow + i)], 1);
}

__global__ __launch_bounds__(1024)
void scan_kernel() {
    __shared__ int sdata[1024];
    const int t = threadIdx.x;
    const int CHUNK = (N_NODES + 1023) / 1024;   // 147
    int begin = t * CHUNK;
    int end   = begin + CHUNK; if (end > N_NODES) end = N_NODES;
    int s = 0;
    for (int i = begin; i < end; i++) s += g_cnt[i];
    sdata[t] = s;
    __syncthreads();
    for (int off = 1; off < 1024; off <<= 1) {
        int v = (t >= off) ? sdata[t - off] : 0;
        __syncthreads();
        sdata[t] += v;
        __syncthreads();
    }
    int run = sdata[t] - s;
    for (int i = begin; i < end; i++) {
        int c = g_cnt[i];
        g_ofs[i] = run;
        g_cur[i] = run;
        run += c;
    }
    if (t == 1023) g_ofs[N_NODES] = sdata[1023];
}

__global__ void scatter_kernel(const int*   __restrict__ erow,
                               const int*   __restrict__ ecol,
                               const float* __restrict__ eval,
                               int n_edges) {
    int i = blockIdx.x * blockDim.x + threadIdx.x;
    if (i < n_edges) {
        int r = __ldg(erow + i);
        int pos = atomicAdd(&g_cur[r], 1);
        g_edges[pos] = make_int2(__ldg(ecol + i),
                                 __float_as_int(__ldg(eval + i)));
    }
}

// ---------------------------------------------------------------------------
// Text GEMM (packed f32x2 FFMA). Writes fp32 g_text0 + fp16 tx words of g_b0.
// BM=128, BN=64, BK=16, 256 threads, 8x4 micro-tile (row pairs packed).
// ---------------------------------------------------------------------------
__global__ void gemm_text_kernel(const float* __restrict__ A,
                                 const float* __restrict__ W,
                                 const float* __restrict__ bias) {
    __shared__ float As[16][132];
    __shared__ float Bs[16][64];

    const int tid = threadIdx.x;
    const int m0  = blockIdx.x * 128;
    const int tr  = tid >> 4;
    const int tc  = tid & 15;

    unsigned long long acc2[4][4];
    #pragma unroll
    for (int ip = 0; ip < 4; ip++)
        #pragma unroll
        for (int j = 0; j < 4; j++) acc2[ip][j] = 0ull;

    for (int k0 = 0; k0 < TEXT_DIM; k0 += 16) {
        #pragma unroll
        for (int p = 0; p < 2; p++) {
            int idx = tid + p * 256;
            int m   = idx >> 2;
            int kq  = idx & 3;
            float4 a4 = make_float4(0.f, 0.f, 0.f, 0.f);
            int gm = m0 + m;
            if (gm < N_NODES)
                a4 = *(const float4*)(A + (size_t)gm * TEXT_DIM + k0 + kq * 4);
            As[kq * 4 + 0][m] = a4.x;
            As[kq * 4 + 1][m] = a4.y;
            As[kq * 4 + 2][m] = a4.z;
            As[kq * 4 + 3][m] = a4.w;
        }
        {
            int k  = tid >> 4;
            int nq = tid & 15;
            float4 b4 = *(const float4*)(W + (size_t)(k0 + k) * 64 + nq * 4);
            *(float4*)&Bs[k][nq * 4] = b4;
        }
        __syncthreads();

        #pragma unroll
        for (int k = 0; k < 16; k++) {
            const unsigned long long* pa =
                (const unsigned long long*)&As[k][tr * 8];
            unsigned long long av[4] = {pa[0], pa[1], pa[2], pa[3]};
            float4 b = *(const float4*)&Bs[k][tc * 4];
            unsigned long long bd[4];
            asm("mov.b64 %0, {%1, %1};" : "=l"(bd[0]) : "r"(__float_as_uint(b.x)));
            asm("mov.b64 %0, {%1, %1};" : "=l"(bd[1]) : "r"(__float_as_uint(b.y)));
            asm("mov.b64 %0, {%1, %1};" : "=l"(bd[2]) : "r"(__float_as_uint(b.z)));
            asm("mov.b64 %0, {%1, %1};" : "=l"(bd[3]) : "r"(__float_as_uint(b.w)));
            #pragma unroll
            for (int ip = 0; ip < 4; ip++)
                #pragma unroll
                for (int j = 0; j < 4; j++)
                    asm("fma.rn.f32x2 %0, %1, %2, %3;"
                        : "=l"(acc2[ip][j])
                        : "l"(av[ip]), "l"(bd[j]), "l"(acc2[ip][j]));
        }
        __syncthreads();
    }

    float4 bv = *(const float4*)(bias + tc * 4);
    #pragma unroll
    for (int ip = 0; ip < 4; ip++) {
        float2 lo_hi[4];
        #pragma unroll
        for (int j = 0; j < 4; j++)
            lo_hi[j] = *reinterpret_cast<float2*>(&acc2[ip][j]);
        #pragma unroll
        for (int half = 0; half < 2; half++) {
            int gm = m0 + tr * 8 + 2 * ip + half;
            if (gm < N_NODES) {
                float4 o;
                o.x = (half ? lo_hi[0].y : lo_hi[0].x) + bv.x;
                o.y = (half ? lo_hi[1].y : lo_hi[1].x) + bv.y;
                o.z = (half ? lo_hi[2].y : lo_hi[2].x) + bv.z;
                o.w = (half ? lo_hi[3].y : lo_hi[3].x) + bv.w;
                *(float4*)(g_text0 + (size_t)gm * 64 + tc * 4) = o;
                g_b0[(size_t)gm * 64 + 4 * tc + 1] = pack_h2(o.x, o.y);
                g_b0[(size_t)gm * 64 + 4 * tc + 3] = pack_h2(o.z, o.w);
            }
        }
    }
}

// ---------------------------------------------------------------------------
// CSR SpMM, fp16 gather, both streams per warp, fp32 accumulate.
// Writes ONLY the fp16 interleaved output (256 B/row).
// ---------------------------------------------------------------------------
__global__ void spmm_csr_kernel(const unsigned* __restrict__ src_b,
                                unsigned* __restrict__ dst_b) {
    int row  = (blockIdx.x * blockDim.x + threadIdx.x) >> 5;
    int lane = threadIdx.x & 31;
    if (row >= N_NODES) return;

    int beg = __ldg(&g_ofs[row]);
    int end = __ldg(&g_ofs[row + 1]);

    const uint2* src = (const uint2*)src_b;

    float2 aid = make_float2(0.f, 0.f);
    float2 atx = make_float2(0.f, 0.f);

    int e = beg;
    for (; e + 4 <= end; e += 4) {
        int2 d0 = __ldg(&g_edges[e + 0]);
        int2 d1 = __ldg(&g_edges[e + 1]);
        int2 d2 = __ldg(&g_edges[e + 2]);
        int2 d3 = __ldg(&g_edges[e + 3]);
        uint2 w0 = __ldg(src + (size_t)d0.x * 32 + lane);
        uint2 w1 = __ldg(src + (size_t)d1.x * 32 + lane);
        uint2 w2 = __ldg(src + (size_t)d2.x * 32 + lane);
        uint2 w3 = __ldg(src + (size_t)d3.x * 32 + lane);
        float v0 = __int_as_float(d0.y), v1 = __int_as_float(d1.y);
        float v2 = __int_as_float(d2.y), v3 = __int_as_float(d3.y);
        float2 f;
        f = unpack_h2(w0.x); aid.x += f.x * v0; aid.y += f.y * v0;
        f = unpack_h2(w0.y); atx.x += f.x * v0; atx.y += f.y * v0;
        f = unpack_h2(w1.x); aid.x += f.x * v1; aid.y += f.y * v1;
        f = unpack_h2(w1.y); atx.x += f.x * v1; atx.y += f.y * v1;
        f = unpack_h2(w2.x); aid.x += f.x * v2; aid.y += f.y * v2;
        f = unpack_h2(w2.y); atx.x += f.x * v2; atx.y += f.y * v2;
        f = unpack_h2(w3.x); aid.x += f.x * v3; aid.y += f.y * v3;
        f = unpack_h2(w3.y); atx.x += f.x * v3; atx.y += f.y * v3;
    }
    for (; e < end; e++) {
        int2 d = __ldg(&g_edges[e]);
        uint2 w = __ldg(src + (size_t)d.x * 32 + lane);
        float v = __int_as_float(d.y);
        float2 f;
        f = unpack_h2(w.x); aid.x += f.x * v; aid.y += f.y * v;
        f = unpack_h2(w.y); atx.x += f.x * v; atx.y += f.y * v;
    }

    uint2 w;
    w.x = pack_h2(aid.x, aid.y);
    w.y = pack_h2(atx.x, atx.y);
    ((uint2*)dst_b)[(size_t)row * 32 + lane] = w;
}

// ---------------------------------------------------------------------------
// Fusion as a register-blocked GEMM: M=150K nodes, K=128, N=64, + epilogue.
// Per 128-node block: assemble As[k=128][m=128] (idf rows 0..63, tf rows
// 64..127) from uemb/iemb + g_text0 (fp32) and g_b1/g_b2 (fp16); W_fuse in
// smem; 8x4 micro-tile with f32x2; sigmoid-gate blend epilogue.
// Dynamic smem: As 128*132*4 + Bs 128*64*4 = 100352 B.
// ---------------------------------------------------------------------------
#define FUSE_SMEM (128 * 132 * 4 + 128 * 64 * 4)
__global__ __launch_bounds__(256)
void fuse_gemm_kernel(const float* __restrict__ uemb,
                      const float* __restrict__ iemb,
                      const int*   __restrict__ tail_mask,
                      const float* __restrict__ W_fuse,
                      const float* __restrict__ b_fuse,
                      const float* __restrict__ tail_amp,
                      float* __restrict__ out) {
    extern __shared__ float sm[];
    float* As = sm;                 // [128][132] k-major
    float* Bs = sm + 128 * 132;     // [128][64]

    const int tid = threadIdx.x;
    const int m0  = blockIdx.x * 128;

    // Load W_fuse (2048 float4)
    #pragma unroll
    for (int p = 0; p < 8; p++) {
        int i = tid + p * 256;
        ((float4*)Bs)[i] = ((const float4*)W_fuse)[i];
    }

    const float amp = 1.f + 1.f / (1.f + __expf(-tail_amp[0]));

    // Assemble As: thread -> node n = tid>>1, pair-range sub = tid&1
    {
        int n    = tid >> 1;
        int node = m0 + n;
        int sub  = tid & 1;
        bool valid = node < N_NODES;
        int nc = valid ? node : 0;
        const float2* id0p = (nc < NUM_USERS)
            ? (const float2*)(uemb + (size_t)nc * 64)
            : (const float2*)(iemb + (size_t)(nc - NUM_USERS) * 64);
        const float2* t0p = (const float2*)(g_text0 + (size_t)nc * 64);
        const uint2*  b1p = (const uint2*)g_b1 + (size_t)nc * 32;
        const uint2*  b2p = (const uint2*)g_b2 + (size_t)nc * 32;
        const float third = 1.f / 3.f;
        float tmul = (valid && __ldg(tail_mask + nc) != 0) ? amp * third : third;
        #pragma unroll 4
        for (int p = 0; p < 16; p++) {
            int pp = sub * 16 + p;          // dim pair 0..31
            float2 i0 = valid ? __ldg(id0p + pp) : make_float2(0.f, 0.f);
            float2 t0 = valid ? __ldg(t0p + pp)  : make_float2(0.f, 0.f);
            uint2 w1 = valid ? __ldg(b1p + pp) : make_uint2(0u, 0u);
            uint2 w2 = valid ? __ldg(b2p + pp) : make_uint2(0u, 0u);
            float2 l1i = unpack_h2(w1.x), l1t = unpack_h2(w1.y);
            float2 l2i = unpack_h2(w2.x), l2t = unpack_h2(w2.y);
            int d = 2 * pp;
            As[(d + 0) * 132 + n]  = (i0.x + l1i.x + l2i.x) * third;
            As[(d + 1) * 132 + n]  = (i0.y + l1i.y + l2i.y) * third;
            As[(64 + d + 0) * 132 + n] = (t0.x + l1t.x + l2t.x) * tmul;
            As[(64 + d + 1) * 132 + n] = (t0.y + l1t.y + l2t.y) * tmul;
        }
    }
    __syncthreads();

    const int tr = tid >> 4;
    const int tc = tid & 15;

    unsigned long long acc2[4][4];
    #pragma unroll
    for (int ip = 0; ip < 4; ip++)
        #pragma unroll
        for (int j = 0; j < 4; j++) acc2[ip][j] = 0ull;

    #pragma unroll 4
    for (int k = 0; k < 128; k++) {
        const unsigned long long* pa =
            (const unsigned long long*)(As + k * 132 + tr * 8);
        unsigned long long av[4] = {pa[0], pa[1], pa[2], pa[3]};
        float4 b = *(const float4*)(Bs + k * 64 + tc * 4);
        unsigned long long bd[4];
        asm("mov.b64 %0, {%1, %1};" : "=l"(bd[0]) : "r"(__float_as_uint(b.x)));
        asm("mov.b64 %0, {%1, %1};" : "=l"(bd[1]) : "r"(__float_as_uint(b.y)));
        asm("mov.b64 %0, {%1, %1};" : "=l"(bd[2]) : "r"(__float_as_uint(b.z)));
        asm("mov.b64 %0, {%1, %1};" : "=l"(bd[3]) : "r"(__float_as_uint(b.w)));
        #pragma unroll
        for (int ip = 0; ip < 4; ip++)
            #pragma unroll
            for (int j = 0; j < 4; j++)
                asm("fma.rn.f32x2 %0, %1, %2, %3;"
                    : "=l"(acc2[ip][j])
                    : "l"(av[ip]), "l"(bd[j]), "l"(acc2[ip][j]));
    }

    float4 bv = *(const float4*)(b_fuse + tc * 4);
    #pragma unroll
    for (int ip = 0; ip < 4; ip++) {
        float2 lo_hi[4];
        #pragma unroll
        for (int j = 0; j < 4; j++)
            lo_hi[j] = *reinterpret_cast<float2*>(&acc2[ip][j]);
        #pragma unroll
        for (int half = 0; half < 2; half++) {
            int m  = tr * 8 + 2 * ip + half;
            int gm = m0 + m;
            if (gm < N_NODES) {
                float4 o;
                float accs[4] = {
                    (half ? lo_hi[0].y : lo_hi[0].x) + bv.x,
                    (half ? lo_hi[1].y : lo_hi[1].x) + bv.y,
                    (half ? lo_hi[2].y : lo_hi[2].x) + bv.z,
                    (half ? lo_hi[3].y : lo_hi[3].x) + bv.w };
                float* po = (float*)&o;
                #pragma unroll
                for (int j = 0; j < 4; j++) {
                    int d = tc * 4 + j;
                    float gate = 1.f / (1.f + __expf(-accs[j]));
                    float idf = As[d * 132 + m];
                    float tf  = As[(64 + d) * 132 + m];
                    po[j] = gate * idf + (1.f - gate) * tf;
                }
                *(float4*)(out + (size_t)gm * 64 + tc * 4) = o;
            }
        }
    }
}

// ---------------------------------------------------------------------------
// Launch. Inputs: 0 text_feats, 1 edge_row, 2 edge_col, 3 edge_val,
// 4 tail_mask(int32), 5 user_emb, 6 item_emb, 7 W_text, 8 b_text,
// 9 W_fuse, 10 b_fuse, 11 tail_amp
// ---------------------------------------------------------------------------
extern "C" void kernel_launch(void* const* d_in, const int* in_sizes, int n_in,
                              void* d_out, int out_size) {
    const float* text_feats = (const float*)d_in[0];
    const int*   edge_row   = (const int*)d_in[1];
    const int*   edge_col   = (const int*)d_in[2];
    const float* edge_val   = (const float*)d_in[3];
    const int*   tail_mask  = (const int*)d_in[4];
    const float* user_emb   = (const float*)d_in[5];
    const float* item_emb   = (const float*)d_in[6];
    const float* W_text     = (const float*)d_in[7];
    const float* b_text     = (const float*)d_in[8];
    const float* W_fuse     = (const float*)d_in[9];
    const float* b_fuse     = (const float*)d_in[10];
    const float* tail_amp   = (const float*)d_in[11];
    float*       out        = (float*)d_out;

    const int n_edges = in_sizes[1];

    unsigned *p_b0, *p_b1, *p_b2;
    cudaGetSymbolAddress((void**)&p_b0, g_b0);
    cudaGetSymbolAddress((void**)&p_b1, g_b1);
    cudaGetSymbolAddress((void**)&p_b2, g_b2);

    static bool attr_set = false;
    if (!attr_set) {
        cudaFuncSetAttribute(fuse_gemm_kernel,
                             cudaFuncAttributeMaxDynamicSharedMemorySize,
                             FUSE_SMEM);
        attr_set = true;
    }

    // 1. prep: fp16 id words + zero histogram
    {
        int n4 = N64 / 4;
        prep_kernel<<<(n4 + 255) / 256, 256>>>(user_emb, item_emb);
    }
    // 2. CSR build
    hist_kernel<<<(n_edges + 255) / 256, 256>>>(edge_row, n_edges);
    scan_kernel<<<1, 1024>>>();
    scatter_kernel<<<(n_edges + 255) / 256, 256>>>(edge_row, edge_col,
                                                   edge_val, n_edges);
    // 3. text GEMM (fp32 + fp16 words)
    gemm_text_kernel<<<(N_NODES + 127) / 128, 256>>>(text_feats, W_text, b_text);
    // 4+5. propagation (fp16 in/out)
    {
        int blocks = (N_NODES * 32 + 255) / 256;
        spmm_csr_kernel<<<blocks, 256>>>(p_b0, p_b1);
        spmm_csr_kernel<<<blocks, 256>>>(p_b1, p_b2);
    }
    // 6. fusion epilogue as register-blocked GEMM
    fuse_gemm_kernel<<<(N_NODES + 127) / 128, 256, FUSE_SMEM>>>(
        user_emb, item_emb, tail_mask, W_fuse, b_fuse, tail_amp, out);
}

// round 8
// speedup vs baseline: 3.7200x; 1.1744x over previous
#include <cuda_runtime.h>
#include <cuda_bf16.h>
#include <cuda_fp16.h>
#include <cstdint>

#define NUM_USERS 100000
#define NUM_ITEMS 50000
#define N_NODES   150000
#define EMB_DIM   64
#define TEXT_DIM  384
#define N64 (N_NODES * EMB_DIM)
#define MAX_EDGES 5000000

// fp32 text projection (exact, used in fusion sums)
__device__ float g_text0[N64];

// fp16 interleaved buffers: per node 64 uint words:
//   uint4 q of a node = (id pair 2q, tx pair 2q, id pair 2q+1, tx pair 2q+1)
__device__ unsigned g_b0[N_NODES * 64];
__device__ unsigned g_b1[N_NODES * 64];
__device__ unsigned g_b2[N_NODES * 64];

// CSR machinery
__device__ int  g_cnt[N_NODES];
__device__ int  g_ofs[N_NODES + 1];
__device__ int  g_cur[N_NODES];
__device__ int2 g_edges[MAX_EDGES];   // (col, val bits), row-sorted

static __device__ __forceinline__ unsigned pack_h2(float a, float b) {
    __half2 h = __floats2half2_rn(a, b);
    return *reinterpret_cast<unsigned*>(&h);
}
static __device__ __forceinline__ float2 unpack_h2(unsigned w) {
    return __half22float2(*reinterpret_cast<__half2*>(&w));
}

// ---------------------------------------------------------------------------
// Prep (main stream): fp16 id words of g_b0 from concat(uemb,iemb).
// ---------------------------------------------------------------------------
__global__ void prep_kernel(const float* __restrict__ uemb,
                            const float* __restrict__ iemb) {
    int i = blockIdx.x * blockDim.x + threadIdx.x;
    const int n4 = N64 / 4;
    const int u4 = NUM_USERS * (EMB_DIM / 4);
    if (i < n4) {
        float4 src = (i < u4) ? ((const float4*)uemb)[i]
                              : ((const float4*)iemb)[i - u4];
        g_b0[4 * i]     = pack_h2(src.x, src.y);
        g_b0[4 * i + 2] = pack_h2(src.z, src.w);
    }
}

// ---------------------------------------------------------------------------
// CSR build (side stream): zero counts, histogram, scan, scatter
// ---------------------------------------------------------------------------
__global__ void zero_cnt_kernel() {
    int i = blockIdx.x * blockDim.x + threadIdx.x;
    if (i < N_NODES / 4)
        ((int4*)g_cnt)[i] = make_int4(0, 0, 0, 0);
}

__global__ void hist_kernel(const int* __restrict__ erow, int n_edges) {
    int i = blockIdx.x * blockDim.x + threadIdx.x;
    if (i < n_edges) atomicAdd(&g_cnt[__ldg(erow + i)], 1);
}

__global__ __launch_bounds__(1024)
void scan_kernel() {
    __shared__ int sdata[1024];
    const int t = threadIdx.x;
    const int CHUNK = (N_NODES + 1023) / 1024;   // 147
    int begin = t * CHUNK;
    int end   = begin + CHUNK; if (end > N_NODES) end = N_NODES;
    int s = 0;
    for (int i = begin; i < end; i++) s += g_cnt[i];
    sdata[t] = s;
    __syncthreads();
    for (int off = 1; off < 1024; off <<= 1) {
        int v = (t >= off) ? sdata[t - off] : 0;
        __syncthreads();
        sdata[t] += v;
        __syncthreads();
    }
    int run = sdata[t] - s;
    for (int i = begin; i < end; i++) {
        int c = g_cnt[i];
        g_ofs[i] = run;
        g_cur[i] = run;
        run += c;
    }
    if (t == 1023) g_ofs[N_NODES] = sdata[1023];
}

__global__ void scatter_kernel(const int*   __restrict__ erow,
                               const int*   __restrict__ ecol,
                               const float* __restrict__ eval,
                               int n_edges) {
    int base = (blockIdx.x * blockDim.x + threadIdx.x) * 4;
    #pragma unroll
    for (int j = 0; j < 4; j++) {
        int i = base + j;
        if (i < n_edges) {
            int r = __ldg(erow + i);
            int pos = atomicAdd(&g_cur[r], 1);
            g_edges[pos] = make_int2(__ldg(ecol + i),
                                     __float_as_int(__ldg(eval + i)));
        }
    }
}

// ---------------------------------------------------------------------------
// Text GEMM (packed f32x2 FFMA). Writes fp32 g_text0 + fp16 tx words of g_b0.
// ---------------------------------------------------------------------------
__global__ void gemm_text_kernel(const float* __restrict__ A,
                                 const float* __restrict__ W,
                                 const float* __restrict__ bias) {
    __shared__ float As[16][132];
    __shared__ float Bs[16][64];

    const int tid = threadIdx.x;
    const int m0  = blockIdx.x * 128;
    const int tr  = tid >> 4;
    const int tc  = tid & 15;

    unsigned long long acc2[4][4];
    #pragma unroll
    for (int ip = 0; ip < 4; ip++)
        #pragma unroll
        for (int j = 0; j < 4; j++) acc2[ip][j] = 0ull;

    for (int k0 = 0; k0 < TEXT_DIM; k0 += 16) {
        #pragma unroll
        for (int p = 0; p < 2; p++) {
            int idx = tid + p * 256;
            int m   = idx >> 2;
            int kq  = idx & 3;
            float4 a4 = make_float4(0.f, 0.f, 0.f, 0.f);
            int gm = m0 + m;
            if (gm < N_NODES)
                a4 = *(const float4*)(A + (size_t)gm * TEXT_DIM + k0 + kq * 4);
            As[kq * 4 + 0][m] = a4.x;
            As[kq * 4 + 1][m] = a4.y;
            As[kq * 4 + 2][m] = a4.z;
            As[kq * 4 + 3][m] = a4.w;
        }
        {
            int k  = tid >> 4;
            int nq = tid & 15;
            float4 b4 = *(const float4*)(W + (size_t)(k0 + k) * 64 + nq * 4);
            *(float4*)&Bs[k][nq * 4] = b4;
        }
        __syncthreads();

        #pragma unroll
        for (int k = 0; k < 16; k++) {
            const unsigned long long* pa =
                (const unsigned long long*)&As[k][tr * 8];
            unsigned long long av[4] = {pa[0], pa[1], pa[2], pa[3]};
            float4 b = *(const float4*)&Bs[k][tc * 4];
            unsigned long long bd[4];
            asm("mov.b64 %0, {%1, %1};" : "=l"(bd[0]) : "r"(__float_as_uint(b.x)));
            asm("mov.b64 %0, {%1, %1};" : "=l"(bd[1]) : "r"(__float_as_uint(b.y)));
            asm("mov.b64 %0, {%1, %1};" : "=l"(bd[2]) : "r"(__float_as_uint(b.z)));
            asm("mov.b64 %0, {%1, %1};" : "=l"(bd[3]) : "r"(__float_as_uint(b.w)));
            #pragma unroll
            for (int ip = 0; ip < 4; ip++)
                #pragma unroll
                for (int j = 0; j < 4; j++)
                    asm("fma.rn.f32x2 %0, %1, %2, %3;"
                        : "=l"(acc2[ip][j])
                        : "l"(av[ip]), "l"(bd[j]), "l"(acc2[ip][j]));
        }
        __syncthreads();
    }

    float4 bv = *(const float4*)(bias + tc * 4);
    #pragma unroll
    for (int ip = 0; ip < 4; ip++) {
        float2 lo_hi[4];
        #pragma unroll
        for (int j = 0; j < 4; j++)
            lo_hi[j] = *reinterpret_cast<float2*>(&acc2[ip][j]);
        #pragma unroll
        for (int half = 0; half < 2; half++) {
            int gm = m0 + tr * 8 + 2 * ip + half;
            if (gm < N_NODES) {
                float4 o;
                o.x = (half ? lo_hi[0].y : lo_hi[0].x) + bv.x;
                o.y = (half ? lo_hi[1].y : lo_hi[1].x) + bv.y;
                o.z = (half ? lo_hi[2].y : lo_hi[2].x) + bv.z;
                o.w = (half ? lo_hi[3].y : lo_hi[3].x) + bv.w;
                *(float4*)(g_text0 + (size_t)gm * 64 + tc * 4) = o;
                g_b0[(size_t)gm * 64 + 4 * tc + 1] = pack_h2(o.x, o.y);
                g_b0[(size_t)gm * 64 + 4 * tc + 3] = pack_h2(o.z, o.w);
            }
        }
    }
}

// ---------------------------------------------------------------------------
// CSR SpMM v2: warp per row; half-warps take even/odd edges; LDG.128 gathers;
// x3 unroll (6 edges in flight per warp); shfl_xor(16) combine; fp16 out.
// ---------------------------------------------------------------------------
#define SPMM_FMA(W, V)                                                        \
    do {                                                                      \
        float2 _f;                                                            \
        _f = unpack_h2((W).x); aid0.x += _f.x * (V); aid0.y += _f.y * (V);    \
        _f = unpack_h2((W).y); atx0.x += _f.x * (V); atx0.y += _f.y * (V);    \
        _f = unpack_h2((W).z); aid1.x += _f.x * (V); aid1.y += _f.y * (V);    \
        _f = unpack_h2((W).w); atx1.x += _f.x * (V); atx1.y += _f.y * (V);    \
    } while (0)

__global__ void spmm_csr_kernel(const unsigned* __restrict__ src_b,
                                unsigned* __restrict__ dst_b) {
    int row  = (blockIdx.x * blockDim.x + threadIdx.x) >> 5;
    int lane = threadIdx.x & 31;
    if (row >= N_NODES) return;

    const int h = lane >> 4;       // half-warp: edge parity
    const int l = lane & 15;       // gather lane (uint4 index within node)

    int beg = __ldg(&g_ofs[row]);
    int end = __ldg(&g_ofs[row + 1]);

    const uint4* src = (const uint4*)src_b;   // node*16 + l

    float2 aid0 = make_float2(0.f, 0.f), atx0 = make_float2(0.f, 0.f);
    float2 aid1 = make_float2(0.f, 0.f), atx1 = make_float2(0.f, 0.f);

    int e = beg + h;
    for (; e + 4 < end; e += 6) {
        int2 d0 = __ldg(&g_edges[e]);
        int2 d1 = __ldg(&g_edges[e + 2]);
        int2 d2 = __ldg(&g_edges[e + 4]);
        uint4 w0 = __ldg(src + (size_t)d0.x * 16 + l);
        uint4 w1 = __ldg(src + (size_t)d1.x * 16 + l);
        uint4 w2 = __ldg(src + (size_t)d2.x * 16 + l);
        float v0 = __int_as_float(d0.y);
        float v1 = __int_as_float(d1.y);
        float v2 = __int_as_float(d2.y);
        SPMM_FMA(w0, v0);
        SPMM_FMA(w1, v1);
        SPMM_FMA(w2, v2);
    }
    while (e < end) {            // at most 2 iterations
        int2 d = __ldg(&g_edges[e]);
        uint4 w = __ldg(src + (size_t)d.x * 16 + l);
        float v = __int_as_float(d.y);
        SPMM_FMA(w, v);
        e += 2;
    }

    // combine even/odd halves
    aid0.x += __shfl_xor_sync(0xffffffffu, aid0.x, 16);
    aid0.y += __shfl_xor_sync(0xffffffffu, aid0.y, 16);
    atx0.x += __shfl_xor_sync(0xffffffffu, atx0.x, 16);
    atx0.y += __shfl_xor_sync(0xffffffffu, atx0.y, 16);
    aid1.x += __shfl_xor_sync(0xffffffffu, aid1.x, 16);
    aid1.y += __shfl_xor_sync(0xffffffffu, aid1.y, 16);
    atx1.x += __shfl_xor_sync(0xffffffffu, atx1.x, 16);
    atx1.y += __shfl_xor_sync(0xffffffffu, atx1.y, 16);

    if (h == 0) {
        uint4 w;
        w.x = pack_h2(aid0.x, aid0.y);
        w.y = pack_h2(atx0.x, atx0.y);
        w.z = pack_h2(aid1.x, aid1.y);
        w.w = pack_h2(atx1.x, atx1.y);
        ((uint4*)dst_b)[(size_t)row * 16 + l] = w;
    }
}

// ---------------------------------------------------------------------------
// Fusion as register-blocked GEMM (M=150K, K=128, N=64) + gate epilogue.
// ---------------------------------------------------------------------------
#define FUSE_SMEM (128 * 132 * 4 + 128 * 64 * 4)
__global__ __launch_bounds__(256)
void fuse_gemm_kernel(const float* __restrict__ uemb,
                      const float* __restrict__ iemb,
                      const int*   __restrict__ tail_mask,
                      const float* __restrict__ W_fuse,
                      const float* __restrict__ b_fuse,
                      const float* __restrict__ tail_amp,
                      float* __restrict__ out) {
    extern __shared__ float sm[];
    float* As = sm;                 // [128][132] k-major
    float* Bs = sm + 128 * 132;     // [128][64]

    const int tid = threadIdx.x;
    const int m0  = blockIdx.x * 128;

    #pragma unroll
    for (int p = 0; p < 8; p++) {
        int i = tid + p * 256;
        ((float4*)Bs)[i] = ((const float4*)W_fuse)[i];
    }

    const float amp = 1.f + 1.f / (1.f + __expf(-tail_amp[0]));

    {
        int n    = tid >> 1;
        int node = m0 + n;
        int sub  = tid & 1;
        bool valid = node < N_NODES;
        int nc = valid ? node : 0;
        const float2* id0p = (nc < NUM_USERS)
            ? (const float2*)(uemb + (size_t)nc * 64)
            : (const float2*)(iemb + (size_t)(nc - NUM_USERS) * 64);
        const float2* t0p = (const float2*)(g_text0 + (size_t)nc * 64);
        const uint2*  b1p = (const uint2*)g_b1 + (size_t)nc * 32;
        const uint2*  b2p = (const uint2*)g_b2 + (size_t)nc * 32;
        const float third = 1.f / 3.f;
        float tmul = (valid && __ldg(tail_mask + nc) != 0) ? amp * third : third;
        #pragma unroll 4
        for (int p = 0; p < 16; p++) {
            int pp = sub * 16 + p;
            float2 i0 = valid ? __ldg(id0p + pp) : make_float2(0.f, 0.f);
            float2 t0 = valid ? __ldg(t0p + pp)  : make_float2(0.f, 0.f);
            uint2 w1 = valid ? __ldg(b1p + pp) : make_uint2(0u, 0u);
            uint2 w2 = valid ? __ldg(b2p + pp) : make_uint2(0u, 0u);
            float2 l1i = unpack_h2(w1.x), l1t = unpack_h2(w1.y);
            float2 l2i = unpack_h2(w2.x), l2t = unpack_h2(w2.y);
            int d = 2 * pp;
            As[(d + 0) * 132 + n]  = (i0.x + l1i.x + l2i.x) * third;
            As[(d + 1) * 132 + n]  = (i0.y + l1i.y + l2i.y) * third;
            As[(64 + d + 0) * 132 + n] = (t0.x + l1t.x + l2t.x) * tmul;
            As[(64 + d + 1) * 132 + n] = (t0.y + l1t.y + l2t.y) * tmul;
        }
    }
    __syncthreads();

    const int tr = tid >> 4;
    const int tc = tid & 15;

    unsigned long long acc2[4][4];
    #pragma unroll
    for (int ip = 0; ip < 4; ip++)
        #pragma unroll
        for (int j = 0; j < 4; j++) acc2[ip][j] = 0ull;

    #pragma unroll 4
    for (int k = 0; k < 128; k++) {
        const unsigned long long* pa =
            (const unsigned long long*)(As + k * 132 + tr * 8);
        unsigned long long av[4] = {pa[0], pa[1], pa[2], pa[3]};
        float4 b = *(const float4*)(Bs + k * 64 + tc * 4);
        unsigned long long bd[4];
        asm("mov.b64 %0, {%1, %1};" : "=l"(bd[0]) : "r"(__float_as_uint(b.x)));
        asm("mov.b64 %0, {%1, %1};" : "=l"(bd[1]) : "r"(__float_as_uint(b.y)));
        asm("mov.b64 %0, {%1, %1};" : "=l"(bd[2]) : "r"(__float_as_uint(b.z)));
        asm("mov.b64 %0, {%1, %1};" : "=l"(bd[3]) : "r"(__float_as_uint(b.w)));
        #pragma unroll
        for (int ip = 0; ip < 4; ip++)
            #pragma unroll
            for (int j = 0; j < 4; j++)
                asm("fma.rn.f32x2 %0, %1, %2, %3;"
                    : "=l"(acc2[ip][j])
                    : "l"(av[ip]), "l"(bd[j]), "l"(acc2[ip][j]));
    }

    float4 bv = *(const float4*)(b_fuse + tc * 4);
    #pragma unroll
    for (int ip = 0; ip < 4; ip++) {
        float2 lo_hi[4];
        #pragma unroll
        for (int j = 0; j < 4; j++)
            lo_hi[j] = *reinterpret_cast<float2*>(&acc2[ip][j]);
        #pragma unroll
        for (int half = 0; half < 2; half++) {
            int m  = tr * 8 + 2 * ip + half;
            int gm = m0 + m;
            if (gm < N_NODES) {
                float4 o;
                float accs[4] = {
                    (half ? lo_hi[0].y : lo_hi[0].x) + bv.x,
                    (half ? lo_hi[1].y : lo_hi[1].x) + bv.y,
                    (half ? lo_hi[2].y : lo_hi[2].x) + bv.z,
                    (half ? lo_hi[3].y : lo_hi[3].x) + bv.w };
                float* po = (float*)&o;
                #pragma unroll
                for (int j = 0; j < 4; j++) {
                    int d = tc * 4 + j;
                    float gate = 1.f / (1.f + __expf(-accs[j]));
                    float idf = As[d * 132 + m];
                    float tf  = As[(64 + d) * 132 + m];
                    po[j] = gate * idf + (1.f - gate) * tf;
                }
                *(float4*)(out + (size_t)gm * 64 + tc * 4) = o;
            }
        }
    }
}

// ---------------------------------------------------------------------------
// Launch: fork a side stream that runs the FULL, self-contained CSR chain
// (zero counts -> hist -> scan -> scatter) while the main stream does
// prep + text GEMM. Join before spmm.
// ---------------------------------------------------------------------------
extern "C" void kernel_launch(void* const* d_in, const int* in_sizes, int n_in,
                              void* d_out, int out_size) {
    const float* text_feats = (const float*)d_in[0];
    const int*   edge_row   = (const int*)d_in[1];
    const int*   edge_col   = (const int*)d_in[2];
    const float* edge_val   = (const float*)d_in[3];
    const int*   tail_mask  = (const int*)d_in[4];
    const float* user_emb   = (const float*)d_in[5];
    const float* item_emb   = (const float*)d_in[6];
    const float* W_text     = (const float*)d_in[7];
    const float* b_text     = (const float*)d_in[8];
    const float* W_fuse     = (const float*)d_in[9];
    const float* b_fuse     = (const float*)d_in[10];
    const float* tail_amp   = (const float*)d_in[11];
    float*       out        = (float*)d_out;

    const int n_edges = in_sizes[1];

    unsigned *p_b0, *p_b1, *p_b2;
    cudaGetSymbolAddress((void**)&p_b0, g_b0);
    cudaGetSymbolAddress((void**)&p_b1, g_b1);
    cudaGetSymbolAddress((void**)&p_b2, g_b2);

    static cudaStream_t s_side = nullptr;
    static cudaEvent_t  ev_fork = nullptr, ev_side = nullptr;
    if (s_side == nullptr) {
        cudaStreamCreateWithFlags(&s_side, cudaStreamNonBlocking);
        cudaEventCreateWithFlags(&ev_fork, cudaEventDisableTiming);
        cudaEventCreateWithFlags(&ev_side, cudaEventDisableTiming);
        cudaFuncSetAttribute(fuse_gemm_kernel,
                             cudaFuncAttributeMaxDynamicSharedMemorySize,
                             FUSE_SMEM);
    }

    // Fork: self-contained CSR build on the side stream
    cudaEventRecord(ev_fork, 0);
    cudaStreamWaitEvent(s_side, ev_fork, 0);
    zero_cnt_kernel<<<(N_NODES / 4 + 255) / 256, 256, 0, s_side>>>();
    hist_kernel<<<(n_edges + 255) / 256, 256, 0, s_side>>>(edge_row, n_edges);
    scan_kernel<<<1, 1024, 0, s_side>>>();
    {
        int threads_needed = (n_edges + 3) / 4;
        scatter_kernel<<<(threads_needed + 255) / 256, 256, 0, s_side>>>(
            edge_row, edge_col, edge_val, n_edges);
    }
    cudaEventRecord(ev_side, s_side);

    // Main stream: prep + text GEMM
    {
        int n4 = N64 / 4;
        prep_kernel<<<(n4 + 255) / 256, 256>>>(user_emb, item_emb);
    }
    gemm_text_kernel<<<(N_NODES + 127) / 128, 256>>>(text_feats, W_text, b_text);

    // Join, then propagate
    cudaStreamWaitEvent(0, ev_side, 0);
    {
        int blocks = (N_NODES * 32 + 255) / 256;
        spmm_csr_kernel<<<blocks, 256>>>(p_b0, p_b1);
        spmm_csr_kernel<<<blocks, 256>>>(p_b1, p_b2);
    }
    // Fusion epilogue
    fuse_gemm_kernel<<<(N_NODES + 127) / 128, 256, FUSE_SMEM>>>(
        user_emb, item_emb, tail_mask, W_fuse, b_fuse, tail_amp, out);
}